// round 16
// baseline (speedup 1.0000x reference)
#include <cuda_runtime.h>
#include <stdint.h>

// ParallelTransport: out[e, c, :] = R(rho[e]) @ x[row[e], c, :]
// x: (1, N, 32, 2) fp32 ; edge_index: (2, E) int32 ; rho: (E,) fp32
// out: (1, E, 32, 2) fp32
//
// R16 = R15 (champion: 63.55 us, DRAM 70.3%) made check-free.
// Each block covers exactly 64 edges = 1024 float4 slots:
//   Stage: threads 0..63 load the block's 64 idx + 64 rho coalesced
//          (4 L1 wavefronts per block vs 8 broadcast LDGs per warp).
//   P2:    4 independent float4 gathers per thread (MLP=4; x table is
//          L2-resident at 12.8 MB).
//   P3:    rotate + __stcs streaming stores (evict-first protects the
//          gather working set in L2; measured best in R12 A/B).
// Main grid has no bounds checks; a tail kernel covers E % 64 edges
// (zero for E = 1.6M). All slot arithmetic is 32-bit.

#define ITER 4
#define TPB  256
#define EDGES_PER_BLK 64   /* TPB*ITER/16 */

__global__ void __launch_bounds__(TPB)
pt_kernel(const float* __restrict__ x,
          const int* __restrict__ row,
          const float* __restrict__ rho,
          float4* __restrict__ out)
{
    __shared__ int   s_idx[EDGES_PER_BLK];
    __shared__ float s_rho[EDGES_PER_BLK];

    unsigned t = threadIdx.x;

    // Stage this block's 64 idx + 64 rho, coalesced (no bounds check:
    // main grid covers only full blocks).
    if (t < EDGES_PER_BLK) {
        unsigned e = blockIdx.x * EDGES_PER_BLK + t;
        s_idx[t] = __ldg(&row[e]);
        s_rho[t] = __ldg(&rho[e]);
    }
    __syncthreads();

    unsigned base = blockIdx.x * (TPB * ITER) + t;
    unsigned sub  = t & 15u;
    unsigned le0  = t >> 4;            // local edge for i=0; +16 per slot

    int    r[ITER];
    float  rv[ITER];
    float4 v[ITER];

    // Phase 1: per-slot idx/rho from smem (broadcast, off the L1tex path)
    #pragma unroll
    for (int i = 0; i < ITER; i++) {
        unsigned le = le0 + i * (TPB / 16);
        r[i]  = s_idx[le];
        rv[i] = s_rho[le];
    }

    // Phase 2: dependent gathers — 4 independent chains in flight
    #pragma unroll
    for (int i = 0; i < ITER; i++) {
        v[i] = __ldg(reinterpret_cast<const float4*>(x)
                     + ((unsigned)r[i] * 16u + sub));
    }

    // Phase 3: rotate + streaming store
    #pragma unroll
    for (int i = 0; i < ITER; i++) {
        float s, c;
        __sincosf(rv[i], &s, &c);
        float4 o;
        o.x = fmaf(c, v[i].x, -s * v[i].y);
        o.y = fmaf(s, v[i].x,  c * v[i].y);
        o.z = fmaf(c, v[i].z, -s * v[i].w);
        o.w = fmaf(s, v[i].z,  c * v[i].w);
        __stcs(&out[base + i * TPB], o);
    }
}

// Tail: per-slot fallback for edges not covered by full blocks (E % 64)
__global__ void __launch_bounds__(TPB)
pt_tail_kernel(const float* __restrict__ x,
               const int* __restrict__ row,
               const float* __restrict__ rho,
               float4* __restrict__ out,
               unsigned start, unsigned total)
{
    unsigned slot = start + blockIdx.x * TPB + threadIdx.x;
    if (slot >= total) return;
    unsigned e = slot >> 4, sub = slot & 15u;
    int   r  = __ldg(&row[e]);
    float rv = __ldg(&rho[e]);
    float s, c;
    __sincosf(rv, &s, &c);
    float4 v = __ldg(reinterpret_cast<const float4*>(x) + ((unsigned)r * 16u + sub));
    float4 o;
    o.x = fmaf(c, v.x, -s * v.y);
    o.y = fmaf(s, v.x,  c * v.y);
    o.z = fmaf(c, v.z, -s * v.w);
    o.w = fmaf(s, v.z,  c * v.w);
    __stcs(&out[slot], o);
}

extern "C" void kernel_launch(void* const* d_in, const int* in_sizes, int n_in,
                              void* d_out, int out_size)
{
    const float* x    = (const float*)d_in[0];
    const int*   eidx = (const int*)d_in[1];   // (2, E): first E entries = row
    const float* rho  = (const float*)d_in[2];

    unsigned E = (unsigned)in_sizes[2];
    unsigned full_blocks   = E / EDGES_PER_BLK;
    unsigned covered_edges = full_blocks * EDGES_PER_BLK;

    if (full_blocks)
        pt_kernel<<<full_blocks, TPB>>>(x, eidx, rho, (float4*)d_out);

    if (covered_edges < E) {
        unsigned start = covered_edges * 16u;
        unsigned total = E * 16u;
        unsigned rem   = total - start;
        unsigned tb    = (rem + TPB - 1) / TPB;
        pt_tail_kernel<<<tb, TPB>>>(x, eidx, rho, (float4*)d_out, start, total);
    }
}